// round 5
// baseline (speedup 1.0000x reference)
#include <cuda_runtime.h>
#include <cuda_bf16.h>
#include <math.h>

// Problem constants
#define BB 4
#define TT 12
#define NN 2048
#define FF 64
#define HH 4
#define DD 16
#define CC 64
#define NROW (BB*NN)          // 8192 rows of graph state
#define TR  (TT*BB*NN)        // 98304 projected rows
#define ADJ_STRIDE 128        // ELL stride (deg mean ~17, P(deg>128) ~ 0)
#define LRELU_SLOPE 0.2f
#define BN_EPS 1e-3f

// -------- device scratch (no allocation allowed) --------
__device__ int   g_adj[NROW * ADJ_STRIDE];     // 4 MB
__device__ int   g_deg[NROW];
__device__ float g_feat[(size_t)TR * 128];     // [R][0:64)=featZ, [64:128)=featH  (50 MB)
__device__ float g_lin [(size_t)TR * 128];     // [R][0:64)=linZ+bz, [64:128)=linH+bh (50 MB)
__device__ float g_att [(size_t)TR * 16];      // [f1Z(4), f2Z(4), f1H(4), f2H(4)]  (6.3 MB)
__device__ float g_H   [(size_t)NROW * CC];    // recurrent state (2 MB)

// =====================================================================
// 1) Build ELL adjacency from bias_mat (edge <=> bias == 0.0f)
// =====================================================================
__global__ __launch_bounds__(256) void adj_build(const float* __restrict__ bias)
{
    int warp = (blockIdx.x * blockDim.x + threadIdx.x) >> 5;
    int lane = threadIdx.x & 31;
    if (warp >= NROW) return;
    const float* row = bias + (size_t)warp * NN;
    int cnt = 0;
    for (int base = 0; base < NN; base += 32) {
        float v = row[base + lane];
        bool e = (v == 0.0f);
        unsigned m = __ballot_sync(0xffffffffu, e);
        if (e) {
            int pos = cnt + __popc(m & ((1u << lane) - 1u));
            if (pos < ADJ_STRIDE) g_adj[warp * ADJ_STRIDE + pos] = base + lane;
        }
        cnt += __popc(m);
    }
    if (lane == 0) g_deg[warp] = min(cnt, ADJ_STRIDE);
}

// =====================================================================
// 2) Fused projection GEMM for ALL timesteps:
//    [T*B*N, 64] x [64, 256]  ->  feats (Z,H), lin (Z,H), and f1/f2 dots
//    thread (m = tid>>6 in {WgZ, WgH, Wz, Wh}, c = tid&63) holds its
//    64-entry weight column in registers; rows streamed via smem.
// =====================================================================
#define ROWS_PER_BLOCK 128
__global__ __launch_bounds__(256) void gemm_all(
    const float* __restrict__ X,
    const float* __restrict__ W_z,  const float* __restrict__ Z_bias,
    const float* __restrict__ W_h,  const float* __restrict__ H_bias,
    const float* __restrict__ Wg_z, const float* __restrict__ a1_z, const float* __restrict__ a2_z,
    const float* __restrict__ Wg_h, const float* __restrict__ a1_h, const float* __restrict__ a2_h)
{
    __shared__ float sx[16 * 64];

    int tid = threadIdx.x;
    int m = tid >> 6, c = tid & 63;
    int h = c >> 4, d = c & 15;

    float w[64];
#pragma unroll
    for (int f = 0; f < 64; f++) {
        if      (m == 0) w[f] = Wg_z[h * 1024 + f * 16 + d];
        else if (m == 1) w[f] = Wg_h[h * 1024 + f * 16 + d];
        else if (m == 2) w[f] = W_z[f * 64 + c];
        else             w[f] = W_h[f * 64 + c];
    }
    float bias = (m == 2) ? Z_bias[c] : ((m == 3) ? H_bias[c] : 0.0f);
    float aa1  = (m == 0) ? a1_z[c]  : ((m == 1) ? a1_h[c] : 0.0f);
    float aa2  = (m == 0) ? a2_z[c]  : ((m == 1) ? a2_h[c] : 0.0f);

    int R0 = blockIdx.x * ROWS_PER_BLOCK;

    for (int tile = 0; tile < ROWS_PER_BLOCK; tile += 16) {
        // stage 16 rows of X into smem (each thread: one float4)
        {
            int rr = R0 + tile + (tid >> 4);
            int t = rr / (BB * NN);
            int rem = rr - t * (BB * NN);
            int b = rem >> 11, n = rem & (NN - 1);
            const float4* xp = (const float4*)(X + (((size_t)(b * TT + t) * NN + n) * FF));
            ((float4*)sx)[(tid >> 4) * 16 + (tid & 15)] = xp[tid & 15];
        }
        __syncthreads();

#pragma unroll 4
        for (int rr = 0; rr < 16; rr++) {
            const float* xr = sx + rr * 64;
            float o0 = 0.f, o1 = 0.f, o2 = 0.f, o3 = 0.f;
#pragma unroll
            for (int f = 0; f < 64; f += 4) {
                float4 xv = *(const float4*)(xr + f);
                o0 = fmaf(xv.x, w[f + 0], o0);
                o1 = fmaf(xv.y, w[f + 1], o1);
                o2 = fmaf(xv.z, w[f + 2], o2);
                o3 = fmaf(xv.w, w[f + 3], o3);
            }
            float o = (o0 + o1) + (o2 + o3);

            size_t R = (size_t)(R0 + tile + rr);
            if (m < 2) {
                g_feat[R * 128 + m * 64 + c] = o;
                // per-head attention dots f1 = feat . a1, f2 = feat . a2
                float s1 = o * aa1, s2 = o * aa2;
#pragma unroll
                for (int off = 8; off; off >>= 1) {
                    s1 += __shfl_xor_sync(0xffffffffu, s1, off, 16);
                    s2 += __shfl_xor_sync(0xffffffffu, s2, off, 16);
                }
                if (d == 0) {
                    g_att[R * 16 + m * 8 + h]     = s1;
                    g_att[R * 16 + m * 8 + 4 + h] = s2;
                }
            } else {
                g_lin[R * 128 + (m - 2) * 64 + c] = o + bias;
            }
        }
        __syncthreads();
    }
}

// =====================================================================
// 3) Per-timestep: sparse GAT softmax (both gates, 4 heads) + GRU update.
//    One warp per graph row. Coefs staged in smem. Last step fuses BN.
// =====================================================================
__device__ __forceinline__ float lrelu(float x) { return x >= 0.f ? x : LRELU_SLOPE * x; }
__device__ __forceinline__ float elu1(float x)  { return x > 0.f ? x : expm1f(x); }

#define SLOT 9   // padded stride (bank-conflict-free)
__global__ __launch_bounds__(256) void attn_step(
    int t,
    const float* __restrict__ bg_z, const float* __restrict__ bg_h,
    const float* __restrict__ bn_gamma, const float* __restrict__ bn_beta,
    const float* __restrict__ bn_mean,  const float* __restrict__ bn_var,
    float* __restrict__ out, int last)
{
    __shared__ float sc[8][ADJ_STRIDE * SLOT];   // 36 KB
    __shared__ int   sadj[8][ADJ_STRIDE];        // 4 KB

    int wid = threadIdx.x >> 5, lane = threadIdx.x & 31;
    int row = blockIdx.x * 8 + wid;              // b*N + n
    int b = row >> 11, n = row & (NN - 1);
    size_t R = (size_t)((t * BB + b) * NN + n);
    size_t sliceAtt  = (size_t)(t * BB + b) * NN * 16;
    size_t sliceFeat = (size_t)(t * BB + b) * NN * 128;

    int deg = g_deg[row];
    for (int j = lane; j < deg; j += 32) sadj[wid][j] = g_adj[row * ADJ_STRIDE + j];
    __syncwarp();

    const float4* attp = (const float4*)(g_att + R * 16);
    float4 f1z = attp[0];
    float4 f1h = attp[2];

    // pass 1: logits -> smem, running per-lane max
    float mz[4] = {-3.4e38f, -3.4e38f, -3.4e38f, -3.4e38f};
    float mh[4] = {-3.4e38f, -3.4e38f, -3.4e38f, -3.4e38f};
    int rounds = (deg + 31) >> 5;
    for (int r = 0; r < rounds; r++) {
        int j = r * 32 + lane;
        if (j < deg) {
            int nj = sadj[wid][j];
            const float* ap = g_att + sliceAtt + (size_t)nj * 16;
            float4 f2z = *(const float4*)(ap + 4);
            float4 f2h = *(const float4*)(ap + 12);
            float lz0 = lrelu(f1z.x + f2z.x), lz1 = lrelu(f1z.y + f2z.y);
            float lz2 = lrelu(f1z.z + f2z.z), lz3 = lrelu(f1z.w + f2z.w);
            float lh0 = lrelu(f1h.x + f2h.x), lh1 = lrelu(f1h.y + f2h.y);
            float lh2 = lrelu(f1h.z + f2h.z), lh3 = lrelu(f1h.w + f2h.w);
            float* s = &sc[wid][j * SLOT];
            s[0] = lz0; s[1] = lz1; s[2] = lz2; s[3] = lz3;
            s[4] = lh0; s[5] = lh1; s[6] = lh2; s[7] = lh3;
            mz[0] = fmaxf(mz[0], lz0); mz[1] = fmaxf(mz[1], lz1);
            mz[2] = fmaxf(mz[2], lz2); mz[3] = fmaxf(mz[3], lz3);
            mh[0] = fmaxf(mh[0], lh0); mh[1] = fmaxf(mh[1], lh1);
            mh[2] = fmaxf(mh[2], lh2); mh[3] = fmaxf(mh[3], lh3);
        }
    }
#pragma unroll
    for (int off = 16; off; off >>= 1) {
#pragma unroll
        for (int k = 0; k < 4; k++) {
            mz[k] = fmaxf(mz[k], __shfl_xor_sync(0xffffffffu, mz[k], off));
            mh[k] = fmaxf(mh[k], __shfl_xor_sync(0xffffffffu, mh[k], off));
        }
    }

    // pass 2: exp(l - m) in place, per-lane sums
    float sz[4] = {0.f, 0.f, 0.f, 0.f};
    float sh[4] = {0.f, 0.f, 0.f, 0.f};
    for (int r = 0; r < rounds; r++) {
        int j = r * 32 + lane;
        if (j < deg) {
            float* s = &sc[wid][j * SLOT];
#pragma unroll
            for (int k = 0; k < 4; k++) {
                float e = expf(s[k] - mz[k]);     s[k] = e;     sz[k] += e;
                float f = expf(s[4 + k] - mh[k]); s[4 + k] = f; sh[k] += f;
            }
        }
    }
#pragma unroll
    for (int off = 16; off; off >>= 1) {
#pragma unroll
        for (int k = 0; k < 4; k++) {
            sz[k] += __shfl_xor_sync(0xffffffffu, sz[k], off);
            sh[k] += __shfl_xor_sync(0xffffffffu, sh[k], off);
        }
    }
    __syncwarp();

    // pass 3: weighted aggregation. lane handles channels c0=lane, c1=lane+32.
    int h0 = lane >> 4;          // head of c0 (0/1), head of c1 is h0+2
    float az0 = 0.f, az1 = 0.f, ah0 = 0.f, ah1 = 0.f;
#pragma unroll 2
    for (int jj = 0; jj < deg; jj++) {
        int nj = sadj[wid][jj];
        const float* s = &sc[wid][jj * SLOT];
        float ez0 = s[h0],     ez1 = s[2 + h0];
        float eh0 = s[4 + h0], eh1 = s[6 + h0];
        const float* fp = g_feat + sliceFeat + (size_t)nj * 128;
        az0 = fmaf(ez0, fp[lane],      az0);
        az1 = fmaf(ez1, fp[32 + lane], az1);
        ah0 = fmaf(eh0, fp[64 + lane], ah0);
        ah1 = fmaf(eh1, fp[96 + lane], ah1);
    }

    float szl0 = (lane & 16) ? sz[1] : sz[0];
    float szl1 = (lane & 16) ? sz[3] : sz[2];
    float shl0 = (lane & 16) ? sh[1] : sh[0];
    float shl1 = (lane & 16) ? sh[3] : sh[2];

    float vz0 = elu1(az0 / szl0 + bg_z[lane]);
    float vz1 = elu1(az1 / szl1 + bg_z[32 + lane]);
    float vh0 = elu1(ah0 / shl0 + bg_h[lane]);
    float vh1 = elu1(ah1 / shl1 + bg_h[32 + lane]);

    // GRU-style update
    const float* lp = g_lin + R * 128;
    size_t hix = (size_t)row * CC;
    float hc0 = g_H[hix + lane], hc1 = g_H[hix + 32 + lane];

    float z0 = 1.f / (1.f + expf(-(vz0 + lp[lane]      + hc0)));
    float z1 = 1.f / (1.f + expf(-(vz1 + lp[32 + lane] + hc1)));
    float t0 = tanhf(vh0 + lp[64 + lane] + hc0);
    float t1 = tanhf(vh1 + lp[96 + lane] + hc1);

    float hn0 = z0 * hc0 + (1.f - z0) * t0;
    float hn1 = z1 * hc1 + (1.f - z1) * t1;
    g_H[hix + lane]      = hn0;
    g_H[hix + 32 + lane] = hn1;

    if (last) {
        int c0 = lane, c1 = 32 + lane;
        out[hix + c0] = (hn0 - bn_mean[c0]) * rsqrtf(bn_var[c0] + BN_EPS) * bn_gamma[c0] + bn_beta[c0];
        out[hix + c1] = (hn1 - bn_mean[c1]) * rsqrtf(bn_var[c1] + BN_EPS) * bn_gamma[c1] + bn_beta[c1];
    }
}

// =====================================================================
// launch
// =====================================================================
extern "C" void kernel_launch(void* const* d_in, const int* in_sizes, int n_in,
                              void* d_out, int out_size)
{
    const float* X      = (const float*)d_in[0];
    const float* bias   = (const float*)d_in[1];
    const float* W_z    = (const float*)d_in[2];
    const float* Z_bias = (const float*)d_in[3];
    const float* W_h    = (const float*)d_in[4];
    const float* H_bias = (const float*)d_in[5];
    const float* Wg_z   = (const float*)d_in[6];
    const float* a1_z   = (const float*)d_in[7];
    const float* a2_z   = (const float*)d_in[8];
    const float* bg_z   = (const float*)d_in[9];
    const float* Wg_h   = (const float*)d_in[10];
    const float* a1_h   = (const float*)d_in[11];
    const float* a2_h   = (const float*)d_in[12];
    const float* bg_h   = (const float*)d_in[13];
    const float* bn_g   = (const float*)d_in[14];
    const float* bn_b   = (const float*)d_in[15];
    const float* bn_m   = (const float*)d_in[16];
    const float* bn_v   = (const float*)d_in[17];
    float* out = (float*)d_out;

    void* hptr = nullptr;
    cudaGetSymbolAddress(&hptr, g_H);
    cudaMemsetAsync(hptr, 0, sizeof(float) * (size_t)NROW * CC);

    adj_build<<<NROW / 8, 256>>>(bias);
    gemm_all<<<TR / ROWS_PER_BLOCK, 256>>>(X, W_z, Z_bias, W_h, H_bias,
                                           Wg_z, a1_z, a2_z, Wg_h, a1_h, a2_h);
    for (int t = 0; t < TT; t++) {
        attn_step<<<NROW / 8, 256>>>(t, bg_z, bg_h, bn_g, bn_b, bn_m, bn_v,
                                     out, t == TT - 1);
    }
}

// round 6
// speedup vs baseline: 1.5952x; 1.5952x over previous
#include <cuda_runtime.h>
#include <cuda_fp16.h>
#include <math.h>

// Problem constants
#define BB 4
#define TT 12
#define NN 2048
#define FF 64
#define CC 64
#define NROW (BB*NN)          // 8192 graph rows
#define TR  (TT*BB*NN)        // 98304 projected rows
#define ADJ_MAX 128           // deg mean ~17, 6-sigma ~42; 128 is safe
#define BN_EPS 1e-3f

// -------- device scratch (no allocation allowed) --------
__device__ __half g_feat[(size_t)TR * 128];   // fp16 feats: [Z(64) | H(64)]  (25 MB)
__device__ float  g_lin [(size_t)TR * 128];   // [linZ+bz (64) | linH+bh (64)] (50 MB)
__device__ float  g_att [(size_t)TR * 16];    // [f1Z(4), f2Z(4), f1H(4), f2H(4)] (6.3 MB)

// =====================================================================
// 1) Fused projection GEMM for ALL timesteps:
//    [T*B*N, 64] x [64, 256] -> feats(fp16), lin(fp32), f1/f2 dots
// =====================================================================
#define ROWS_PER_BLOCK 128
__global__ __launch_bounds__(256) void gemm_all(
    const float* __restrict__ X,
    const float* __restrict__ W_z,  const float* __restrict__ Z_bias,
    const float* __restrict__ W_h,  const float* __restrict__ H_bias,
    const float* __restrict__ Wg_z, const float* __restrict__ a1_z, const float* __restrict__ a2_z,
    const float* __restrict__ Wg_h, const float* __restrict__ a1_h, const float* __restrict__ a2_h)
{
    __shared__ float sx[16 * 64];

    int tid = threadIdx.x;
    int m = tid >> 6, c = tid & 63;
    int h = c >> 4, d = c & 15;

    float w[64];
#pragma unroll
    for (int f = 0; f < 64; f++) {
        if      (m == 0) w[f] = Wg_z[h * 1024 + f * 16 + d];
        else if (m == 1) w[f] = Wg_h[h * 1024 + f * 16 + d];
        else if (m == 2) w[f] = W_z[f * 64 + c];
        else             w[f] = W_h[f * 64 + c];
    }
    float bias = (m == 2) ? Z_bias[c] : ((m == 3) ? H_bias[c] : 0.0f);
    float aa1  = (m == 0) ? a1_z[c]  : ((m == 1) ? a1_h[c] : 0.0f);
    float aa2  = (m == 0) ? a2_z[c]  : ((m == 1) ? a2_h[c] : 0.0f);

    int R0 = blockIdx.x * ROWS_PER_BLOCK;

    for (int tile = 0; tile < ROWS_PER_BLOCK; tile += 16) {
        {
            int rr = R0 + tile + (tid >> 4);
            int t = rr / (BB * NN);
            int rem = rr - t * (BB * NN);
            int b = rem >> 11, n = rem & (NN - 1);
            const float4* xp = (const float4*)(X + (((size_t)(b * TT + t) * NN + n) * FF));
            ((float4*)sx)[(tid >> 4) * 16 + (tid & 15)] = xp[tid & 15];
        }
        __syncthreads();

#pragma unroll 4
        for (int rr = 0; rr < 16; rr++) {
            const float* xr = sx + rr * 64;
            float o0 = 0.f, o1 = 0.f, o2 = 0.f, o3 = 0.f;
#pragma unroll
            for (int f = 0; f < 64; f += 4) {
                float4 xv = *(const float4*)(xr + f);
                o0 = fmaf(xv.x, w[f + 0], o0);
                o1 = fmaf(xv.y, w[f + 1], o1);
                o2 = fmaf(xv.z, w[f + 2], o2);
                o3 = fmaf(xv.w, w[f + 3], o3);
            }
            float o = (o0 + o1) + (o2 + o3);

            size_t R = (size_t)(R0 + tile + rr);
            if (m < 2) {
                g_feat[R * 128 + m * 64 + c] = __float2half(o);
                float s1 = o * aa1, s2 = o * aa2;
#pragma unroll
                for (int off = 8; off; off >>= 1) {
                    s1 += __shfl_xor_sync(0xffffffffu, s1, off, 16);
                    s2 += __shfl_xor_sync(0xffffffffu, s2, off, 16);
                }
                if (d == 0) {
                    g_att[R * 16 + m * 8 + h]     = s1;
                    g_att[R * 16 + m * 8 + 4 + h] = s2;
                }
            } else {
                g_lin[R * 128 + (m - 2) * 64 + c] = o + bias;
            }
        }
        __syncthreads();
    }
}

// =====================================================================
// 2) Fully fused RNN: per warp = one graph row, loops over all 12 t.
//    Adjacency built in-kernel; h carried in registers; no max pass;
//    lane owns 4 contiguous channels -> one coef per neighbor per lane.
// =====================================================================
__device__ __forceinline__ float lrelu_f(float x) { return fmaxf(x, 0.2f * x); }

#define WPB 8
#define ESTRIDE 9   // padded coef slot stride (conflict-free)

__global__ __launch_bounds__(256) void fused_rnn(
    const float* __restrict__ bias,
    const float* __restrict__ bg_z, const float* __restrict__ bg_h,
    const float* __restrict__ bn_g, const float* __restrict__ bn_b,
    const float* __restrict__ bn_m, const float* __restrict__ bn_v,
    float* __restrict__ out)
{
    __shared__ int   sadj[WPB][ADJ_MAX];
    __shared__ float sE[WPB][32 * ESTRIDE];

    int wid  = threadIdx.x >> 5, lane = threadIdx.x & 31;
    int row  = blockIdx.x * WPB + wid;           // b*N + n
    int b    = row >> 11;
    int l16  = lane & 15;

    // ---- build adjacency list for this row (edge <=> bias == 0) ----
    int deg;
    {
        const float4* brow = (const float4*)(bias + (size_t)row * NN);
        int cnt = 0;
        unsigned lm = (1u << lane) - 1u;
        for (int base = 0; base < NN / 4; base += 32) {
            float4 v = brow[base + lane];
            bool e0 = (v.x == 0.f), e1 = (v.y == 0.f), e2 = (v.z == 0.f), e3 = (v.w == 0.f);
            unsigned m0 = __ballot_sync(0xffffffffu, e0);
            unsigned m1 = __ballot_sync(0xffffffffu, e1);
            unsigned m2 = __ballot_sync(0xffffffffu, e2);
            unsigned m3 = __ballot_sync(0xffffffffu, e3);
            int pos = cnt + __popc(m0 & lm) + __popc(m1 & lm) + __popc(m2 & lm) + __popc(m3 & lm);
            int i0 = (base + lane) * 4;
            if (e0 && pos < ADJ_MAX) sadj[wid][pos++] = i0;
            if (e1 && pos < ADJ_MAX) sadj[wid][pos++] = i0 + 1;
            if (e2 && pos < ADJ_MAX) sadj[wid][pos++] = i0 + 2;
            if (e3 && pos < ADJ_MAX) sadj[wid][pos++] = i0 + 3;
            cnt += __popc(m0) + __popc(m1) + __popc(m2) + __popc(m3);
        }
        deg = min(cnt, ADJ_MAX);
    }
    __syncwarp();

    // per-lane constants: GAT output bias for this lane's 4 channels
    float4 bg4 = (lane < 16) ? *(const float4*)(bg_z + 4 * l16)
                             : *(const float4*)(bg_h + 4 * l16);
    int eidx = lane >> 2;            // fixed (gate,head) coef index 0..7

    float4 hc4 = make_float4(0.f, 0.f, 0.f, 0.f);   // live on lanes<16

    for (int t = 0; t < TT; t++) {
        size_t R     = (size_t)t * (BB * NN) + row;
        size_t slice = (size_t)t * (BB * NN) + (size_t)b * NN;

        const float4* ar = (const float4*)(g_att + R * 16);
        float4 f1z = ar[0];
        float4 f1h = ar[2];

        float4 acc = make_float4(0.f, 0.f, 0.f, 0.f);
        float  se  = 0.f;

        for (int c0 = 0; c0 < deg; c0 += 32) {
            int j = c0 + lane;
            if (j < deg) {
                int nj = sadj[wid][j];
                const float4* ap = (const float4*)(g_att + (slice + nj) * 16);
                float4 f2z = ap[1];
                float4 f2h = ap[3];
                float* sp = &sE[wid][lane * ESTRIDE];
                sp[0] = __expf(lrelu_f(f1z.x + f2z.x));
                sp[1] = __expf(lrelu_f(f1z.y + f2z.y));
                sp[2] = __expf(lrelu_f(f1z.z + f2z.z));
                sp[3] = __expf(lrelu_f(f1z.w + f2z.w));
                sp[4] = __expf(lrelu_f(f1h.x + f2h.x));
                sp[5] = __expf(lrelu_f(f1h.y + f2h.y));
                sp[6] = __expf(lrelu_f(f1h.z + f2h.z));
                sp[7] = __expf(lrelu_f(f1h.w + f2h.w));
            }
            __syncwarp();

            int cl = min(deg - c0, 32);
            const float* ep = &sE[wid][eidx];
#pragma unroll 4
            for (int jj = 0; jj < cl; jj++) {
                int nj = sadj[wid][c0 + jj];
                float e = ep[jj * ESTRIDE];
                uint2 raw = *(const uint2*)(g_feat + (slice + nj) * 128 + 4 * lane);
                float2 f01 = __half22float2(*(__half2*)&raw.x);
                float2 f23 = __half22float2(*(__half2*)&raw.y);
                acc.x = fmaf(e, f01.x, acc.x);
                acc.y = fmaf(e, f01.y, acc.y);
                acc.z = fmaf(e, f23.x, acc.z);
                acc.w = fmaf(e, f23.y, acc.w);
                se += e;
            }
            __syncwarp();
        }

        // softmax-normalize, add bias, ELU
        float rse = __fdividef(1.f, se);
        float4 v;
        v.x = acc.x * rse + bg4.x;
        v.y = acc.y * rse + bg4.y;
        v.z = acc.z * rse + bg4.z;
        v.w = acc.w * rse + bg4.w;
        v.x = (v.x > 0.f) ? v.x : (__expf(v.x) - 1.f);
        v.y = (v.y > 0.f) ? v.y : (__expf(v.y) - 1.f);
        v.z = (v.z > 0.f) ? v.z : (__expf(v.z) - 1.f);
        v.w = (v.w > 0.f) ? v.w : (__expf(v.w) - 1.f);

        // broadcast h to upper half
        float4 hcu;
        hcu.x = __shfl_xor_sync(0xffffffffu, hc4.x, 16);
        hcu.y = __shfl_xor_sync(0xffffffffu, hc4.y, 16);
        hcu.z = __shfl_xor_sync(0xffffffffu, hc4.z, 16);
        hcu.w = __shfl_xor_sync(0xffffffffu, hc4.w, 16);
        float4 hcv = (lane < 16) ? hc4 : hcu;

        // add linear part + h, apply gate nonlinearity (branchless
        // sigmoid/tanh unification: a=1 -> sigmoid, a=2 -> tanh)
        float4 linv = *(const float4*)(g_lin + R * 128 + 4 * lane);
        float a  = (lane < 16) ? 1.f : 2.f;
        float am = a - 1.f;
        float4 g;
        {
            float p;
            p = v.x + linv.x + hcv.x; g.x = __fdividef(a, 1.f + __expf(-a * p)) - am;
            p = v.y + linv.y + hcv.y; g.y = __fdividef(a, 1.f + __expf(-a * p)) - am;
            p = v.z + linv.z + hcv.z; g.z = __fdividef(a, 1.f + __expf(-a * p)) - am;
            p = v.w + linv.w + hcv.w; g.w = __fdividef(a, 1.f + __expf(-a * p)) - am;
        }

        // exchange: lanes<16 hold z, receive tanh from partner
        float4 og;
        og.x = __shfl_xor_sync(0xffffffffu, g.x, 16);
        og.y = __shfl_xor_sync(0xffffffffu, g.y, 16);
        og.z = __shfl_xor_sync(0xffffffffu, g.z, 16);
        og.w = __shfl_xor_sync(0xffffffffu, g.w, 16);

        if (lane < 16) {
            hc4.x = g.x * hc4.x + (1.f - g.x) * og.x;
            hc4.y = g.y * hc4.y + (1.f - g.y) * og.y;
            hc4.z = g.z * hc4.z + (1.f - g.z) * og.z;
            hc4.w = g.w * hc4.w + (1.f - g.w) * og.w;
        }
    }

    // BatchNorm epilogue + store (lanes<16 own the 64 channels)
    if (lane < 16) {
        float4 mu = *(const float4*)(bn_m + 4 * l16);
        float4 vr = *(const float4*)(bn_v + 4 * l16);
        float4 ga = *(const float4*)(bn_g + 4 * l16);
        float4 be = *(const float4*)(bn_b + 4 * l16);
        float4 o;
        o.x = (hc4.x - mu.x) * rsqrtf(vr.x + BN_EPS) * ga.x + be.x;
        o.y = (hc4.y - mu.y) * rsqrtf(vr.y + BN_EPS) * ga.y + be.y;
        o.z = (hc4.z - mu.z) * rsqrtf(vr.z + BN_EPS) * ga.z + be.z;
        o.w = (hc4.w - mu.w) * rsqrtf(vr.w + BN_EPS) * ga.w + be.w;
        *(float4*)(out + (size_t)row * CC + 4 * l16) = o;
    }
}

// =====================================================================
// launch
// =====================================================================
extern "C" void kernel_launch(void* const* d_in, const int* in_sizes, int n_in,
                              void* d_out, int out_size)
{
    const float* X      = (const float*)d_in[0];
    const float* bias   = (const float*)d_in[1];
    const float* W_z    = (const float*)d_in[2];
    const float* Z_bias = (const float*)d_in[3];
    const float* W_h    = (const float*)d_in[4];
    const float* H_bias = (const float*)d_in[5];
    const float* Wg_z   = (const float*)d_in[6];
    const float* a1_z   = (const float*)d_in[7];
    const float* a2_z   = (const float*)d_in[8];
    const float* bg_z   = (const float*)d_in[9];
    const float* Wg_h   = (const float*)d_in[10];
    const float* a1_h   = (const float*)d_in[11];
    const float* a2_h   = (const float*)d_in[12];
    const float* bg_h   = (const float*)d_in[13];
    const float* bn_g   = (const float*)d_in[14];
    const float* bn_b   = (const float*)d_in[15];
    const float* bn_m   = (const float*)d_in[16];
    const float* bn_v   = (const float*)d_in[17];
    float* out = (float*)d_out;

    gemm_all<<<TR / ROWS_PER_BLOCK, 256>>>(X, W_z, Z_bias, W_h, H_bias,
                                           Wg_z, a1_z, a2_z, Wg_h, a1_h, a2_h);
    fused_rnn<<<NROW / WPB, 256>>>(bias, bg_z, bg_h, bn_g, bn_b, bn_m, bn_v, out);
}

// round 7
// speedup vs baseline: 2.9180x; 1.8292x over previous
#include <cuda_runtime.h>
#include <cuda_fp16.h>
#include <math.h>

// Problem constants
#define BB 4
#define TT 12
#define NN 2048
#define FF 64
#define CC 64
#define NROW (BB*NN)          // 8192 graph rows
#define TR  (TT*BB*NN)        // 98304 projected rows
#define NTILES (TR/16)        // 6144 m-tiles of 16 rows
#define ADJ_MAX 128
#define BN_EPS 1e-3f

// -------- device scratch (no allocation allowed) --------
__device__ __half    g_feat[(size_t)TR * 128];   // fp16 feats [Z|H]      (25 MB)
__device__ float     g_lin [(size_t)TR * 128];   // fp32 lin [Z+bz|H+bh]  (50 MB)
__device__ float     g_att [(size_t)TR * 16];    // [f1Z4,f2Z4,f1H4,f2H4] (6.3 MB)
__device__ unsigned  g_wfrag[8 * 32 * 32 * 2];   // tf32 B-fragments      (64 KB)

__device__ __forceinline__ unsigned f2tf32(float f) {
    unsigned u;
    asm("cvt.rna.tf32.f32 %0, %1;" : "=r"(u) : "f"(f));
    return u;
}

// =====================================================================
// 0) Prep: shuffle combined weight matrix [64 x 256] into per-lane
//    mma B-fragment layout (rna-rounded tf32).
//    combined col c: [0,64)=WgZ, [64,128)=WgH, [128,192)=Wz, [192,256)=Wh
// =====================================================================
__global__ __launch_bounds__(256) void prep_wfrag(
    const float* __restrict__ W_z,  const float* __restrict__ W_h,
    const float* __restrict__ Wg_z, const float* __restrict__ Wg_h)
{
    int tid = blockIdx.x * blockDim.x + threadIdx.x;   // 0..8191
    int lane = tid & 31;
    int ntg  = (tid >> 5) & 31;
    int kk   = tid >> 10;
    int g = lane >> 2, t = lane & 3;
    int col = ntg * 8 + g;
    int k0 = kk * 8 + t, k1 = k0 + 4;

    float b0, b1;
    if (col < 64) {
        int h = col >> 4, d = col & 15;
        b0 = Wg_z[h * 1024 + k0 * 16 + d];
        b1 = Wg_z[h * 1024 + k1 * 16 + d];
    } else if (col < 128) {
        int c = col - 64; int h = c >> 4, d = c & 15;
        b0 = Wg_h[h * 1024 + k0 * 16 + d];
        b1 = Wg_h[h * 1024 + k1 * 16 + d];
    } else if (col < 192) {
        int c = col - 128;
        b0 = W_z[k0 * 64 + c];
        b1 = W_z[k1 * 64 + c];
    } else {
        int c = col - 192;
        b0 = W_h[k0 * 64 + c];
        b1 = W_h[k1 * 64 + c];
    }
    g_wfrag[tid * 2]     = f2tf32(b0);
    g_wfrag[tid * 2 + 1] = f2tf32(b1);
}

// =====================================================================
// 1) Tensor-core projection GEMM: [98304,64] x [64,256] (tf32 mma)
//    block = 8 warps; warp w: m16 x n32 (n-slice w*32); grid-stride m.
// =====================================================================
#define XPAD 68   // smem row stride (floats) -> conflict-free A frags

__global__ __launch_bounds__(256, 3) void gemm_tc(
    const float* __restrict__ X,
    const float* __restrict__ Z_bias, const float* __restrict__ H_bias,
    const float* __restrict__ a1_z,   const float* __restrict__ a2_z,
    const float* __restrict__ a1_h,   const float* __restrict__ a2_h)
{
    __shared__ float sx[2][16 * XPAD];

    int tid  = threadIdx.x;
    int w    = tid >> 5, lane = tid & 31;
    int g    = lane >> 2, t = lane & 3;

    // ---- per-lane epilogue constants ----
    float av1[4][2], av2[4][2];    // attention vectors  (warps 0-3)
    float bl[4][2];                // linear bias        (warps 4-7)
    if (w < 4) {
        const float* a1p = (w < 2) ? a1_z : a1_h;
        const float* a2p = (w < 2) ? a2_z : a2_h;
#pragma unroll
        for (int nt = 0; nt < 4; nt++) {
            int cm = (w & 1) * 32 + nt * 8 + 2 * t;
            av1[nt][0] = a1p[cm];     av1[nt][1] = a1p[cm + 1];
            av2[nt][0] = a2p[cm];     av2[nt][1] = a2p[cm + 1];
        }
    } else {
#pragma unroll
        for (int nt = 0; nt < 4; nt++) {
            int cl = (w - 4) * 32 + nt * 8 + 2 * t;
            if (cl < 64) { bl[nt][0] = Z_bias[cl];      bl[nt][1] = Z_bias[cl + 1]; }
            else         { bl[nt][0] = H_bias[cl - 64]; bl[nt][1] = H_bias[cl - 63]; }
        }
    }

    // staging role for this thread: row rr, float4 column c4
    int srr = tid >> 4, sc4 = tid & 15;

    int buf = 0;
    // prologue: stage first tile
    {
        int r = blockIdx.x * 16 + srr;
        int tt = r / (BB * NN);
        int rem = r - tt * (BB * NN);
        int b = rem >> 11, n = rem & (NN - 1);
        const float4* xp = (const float4*)(X + (((size_t)(b * TT + tt) * NN + n) * FF));
        *(float4*)(sx[0] + srr * XPAD + sc4 * 4) = xp[sc4];
    }

    for (int tile = blockIdx.x; tile < NTILES; tile += gridDim.x) {
        __syncthreads();   // staged tile visible; previous buf free for overwrite

        // prefetch next tile into other buffer
        int nxt = tile + gridDim.x;
        if (nxt < NTILES) {
            int r = nxt * 16 + srr;
            int tt = r / (BB * NN);
            int rem = r - tt * (BB * NN);
            int b = rem >> 11, n = rem & (NN - 1);
            const float4* xp = (const float4*)(X + (((size_t)(b * TT + tt) * NN + n) * FF));
            *(float4*)(sx[buf ^ 1] + srr * XPAD + sc4 * 4) = xp[sc4];
        }

        // ---- mma over K=64 (8 k-steps), 4 n-tiles ----
        float c[4][4];
#pragma unroll
        for (int nt = 0; nt < 4; nt++)
#pragma unroll
            for (int i = 0; i < 4; i++) c[nt][i] = 0.f;

        const float* xb = sx[buf];
#pragma unroll
        for (int kk = 0; kk < 8; kk++) {
            unsigned ua0 = f2tf32(xb[g * XPAD + kk * 8 + t]);
            unsigned ua1 = f2tf32(xb[(g + 8) * XPAD + kk * 8 + t]);
            unsigned ua2 = f2tf32(xb[g * XPAD + kk * 8 + t + 4]);
            unsigned ua3 = f2tf32(xb[(g + 8) * XPAD + kk * 8 + t + 4]);
#pragma unroll
            for (int nt = 0; nt < 4; nt++) {
                uint2 bf = *(const uint2*)(g_wfrag + ((kk * 32 + (w * 4 + nt)) * 32 + lane) * 2);
                asm volatile(
                    "mma.sync.aligned.m16n8k8.row.col.f32.tf32.tf32.f32 "
                    "{%0,%1,%2,%3},{%4,%5,%6,%7},{%8,%9},{%0,%1,%2,%3};"
                    : "+f"(c[nt][0]), "+f"(c[nt][1]), "+f"(c[nt][2]), "+f"(c[nt][3])
                    : "r"(ua0), "r"(ua1), "r"(ua2), "r"(ua3), "r"(bf.x), "r"(bf.y));
            }
        }

        // ---- epilogue ----
        size_t R0 = (size_t)tile * 16 + g;
        size_t R1 = R0 + 8;

        if (w < 4) {
            // feats -> fp16
#pragma unroll
            for (int nt = 0; nt < 4; nt++) {
                int cp = w * 32 + nt * 8 + 2 * t;
                *(__half2*)(g_feat + R0 * 128 + cp) = __floats2half2_rn(c[nt][0], c[nt][1]);
                *(__half2*)(g_feat + R1 * 128 + cp) = __floats2half2_rn(c[nt][2], c[nt][3]);
            }
            // attention dots f1/f2 (2 heads per warp)
            float p1r0[2] = {0.f, 0.f}, p1r1[2] = {0.f, 0.f};
            float p2r0[2] = {0.f, 0.f}, p2r1[2] = {0.f, 0.f};
#pragma unroll
            for (int nt = 0; nt < 4; nt++) {
                int hh = nt >> 1;
                p1r0[hh] += c[nt][0] * av1[nt][0] + c[nt][1] * av1[nt][1];
                p1r1[hh] += c[nt][2] * av1[nt][0] + c[nt][3] * av1[nt][1];
                p2r0[hh] += c[nt][0] * av2[nt][0] + c[nt][1] * av2[nt][1];
                p2r1[hh] += c[nt][2] * av2[nt][0] + c[nt][3] * av2[nt][1];
            }
#pragma unroll
            for (int off = 1; off <= 2; off <<= 1) {
#pragma unroll
                for (int hh = 0; hh < 2; hh++) {
                    p1r0[hh] += __shfl_xor_sync(0xffffffffu, p1r0[hh], off);
                    p1r1[hh] += __shfl_xor_sync(0xffffffffu, p1r1[hh], off);
                    p2r0[hh] += __shfl_xor_sync(0xffffffffu, p2r0[hh], off);
                    p2r1[hh] += __shfl_xor_sync(0xffffffffu, p2r1[hh], off);
                }
            }
            if (t == 0) {
                int gate = w >> 1, hb = (w & 1) * 2;
#pragma unroll
                for (int hh = 0; hh < 2; hh++) {
                    g_att[R0 * 16 + gate * 8 + hb + hh]     = p1r0[hh];
                    g_att[R0 * 16 + gate * 8 + 4 + hb + hh] = p2r0[hh];
                    g_att[R1 * 16 + gate * 8 + hb + hh]     = p1r1[hh];
                    g_att[R1 * 16 + gate * 8 + 4 + hb + hh] = p2r1[hh];
                }
            }
        } else {
            // linear part + bias -> fp32
#pragma unroll
            for (int nt = 0; nt < 4; nt++) {
                int cl = (w - 4) * 32 + nt * 8 + 2 * t;
                float2 v0 = make_float2(c[nt][0] + bl[nt][0], c[nt][1] + bl[nt][1]);
                float2 v1 = make_float2(c[nt][2] + bl[nt][0], c[nt][3] + bl[nt][1]);
                *(float2*)(g_lin + R0 * 128 + cl) = v0;
                *(float2*)(g_lin + R1 * 128 + cl) = v1;
            }
        }
        buf ^= 1;
    }
}

// =====================================================================
// 2) Fully fused RNN (unchanged from R5): warp = graph row, t in regs.
// =====================================================================
__device__ __forceinline__ float lrelu_f(float x) { return fmaxf(x, 0.2f * x); }

#define WPB 8
#define ESTRIDE 9

__global__ __launch_bounds__(256) void fused_rnn(
    const float* __restrict__ bias,
    const float* __restrict__ bg_z, const float* __restrict__ bg_h,
    const float* __restrict__ bn_g, const float* __restrict__ bn_b,
    const float* __restrict__ bn_m, const float* __restrict__ bn_v,
    float* __restrict__ out)
{
    __shared__ int   sadj[WPB][ADJ_MAX];
    __shared__ float sE[WPB][32 * ESTRIDE];

    int wid  = threadIdx.x >> 5, lane = threadIdx.x & 31;
    int row  = blockIdx.x * WPB + wid;
    int b    = row >> 11;
    int l16  = lane & 15;

    int deg;
    {
        const float4* brow = (const float4*)(bias + (size_t)row * NN);
        int cnt = 0;
        unsigned lm = (1u << lane) - 1u;
        for (int base = 0; base < NN / 4; base += 32) {
            float4 v = brow[base + lane];
            bool e0 = (v.x == 0.f), e1 = (v.y == 0.f), e2 = (v.z == 0.f), e3 = (v.w == 0.f);
            unsigned m0 = __ballot_sync(0xffffffffu, e0);
            unsigned m1 = __ballot_sync(0xffffffffu, e1);
            unsigned m2 = __ballot_sync(0xffffffffu, e2);
            unsigned m3 = __ballot_sync(0xffffffffu, e3);
            int pos = cnt + __popc(m0 & lm) + __popc(m1 & lm) + __popc(m2 & lm) + __popc(m3 & lm);
            int i0 = (base + lane) * 4;
            if (e0 && pos < ADJ_MAX) sadj[wid][pos++] = i0;
            if (e1 && pos < ADJ_MAX) sadj[wid][pos++] = i0 + 1;
            if (e2 && pos < ADJ_MAX) sadj[wid][pos++] = i0 + 2;
            if (e3 && pos < ADJ_MAX) sadj[wid][pos++] = i0 + 3;
            cnt += __popc(m0) + __popc(m1) + __popc(m2) + __popc(m3);
        }
        deg = min(cnt, ADJ_MAX);
    }
    __syncwarp();

    float4 bg4 = (lane < 16) ? *(const float4*)(bg_z + 4 * l16)
                             : *(const float4*)(bg_h + 4 * l16);
    int eidx = lane >> 2;

    float4 hc4 = make_float4(0.f, 0.f, 0.f, 0.f);

    for (int t = 0; t < TT; t++) {
        size_t R     = (size_t)t * (BB * NN) + row;
        size_t slice = (size_t)t * (BB * NN) + (size_t)b * NN;

        const float4* ar = (const float4*)(g_att + R * 16);
        float4 f1z = ar[0];
        float4 f1h = ar[2];

        float4 acc = make_float4(0.f, 0.f, 0.f, 0.f);
        float  se  = 0.f;

        for (int c0 = 0; c0 < deg; c0 += 32) {
            int j = c0 + lane;
            if (j < deg) {
                int nj = sadj[wid][j];
                const float4* ap = (const float4*)(g_att + (slice + nj) * 16);
                float4 f2z = ap[1];
                float4 f2h = ap[3];
                float* sp = &sE[wid][lane * ESTRIDE];
                sp[0] = __expf(lrelu_f(f1z.x + f2z.x));
                sp[1] = __expf(lrelu_f(f1z.y + f2z.y));
                sp[2] = __expf(lrelu_f(f1z.z + f2z.z));
                sp[3] = __expf(lrelu_f(f1z.w + f2z.w));
                sp[4] = __expf(lrelu_f(f1h.x + f2h.x));
                sp[5] = __expf(lrelu_f(f1h.y + f2h.y));
                sp[6] = __expf(lrelu_f(f1h.z + f2h.z));
                sp[7] = __expf(lrelu_f(f1h.w + f2h.w));
            }
            __syncwarp();

            int cl = min(deg - c0, 32);
            const float* ep = &sE[wid][eidx];
#pragma unroll 4
            for (int jj = 0; jj < cl; jj++) {
                int nj = sadj[wid][c0 + jj];
                float e = ep[jj * ESTRIDE];
                uint2 raw = *(const uint2*)(g_feat + (slice + nj) * 128 + 4 * lane);
                float2 f01 = __half22float2(*(__half2*)&raw.x);
                float2 f23 = __half22float2(*(__half2*)&raw.y);
                acc.x = fmaf(e, f01.x, acc.x);
                acc.y = fmaf(e, f01.y, acc.y);
                acc.z = fmaf(e, f23.x, acc.z);
                acc.w = fmaf(e, f23.y, acc.w);
                se += e;
            }
            __syncwarp();
        }

        float rse = __fdividef(1.f, se);
        float4 v;
        v.x = acc.x * rse + bg4.x;
        v.y = acc.y * rse + bg4.y;
        v.z = acc.z * rse + bg4.z;
        v.w = acc.w * rse + bg4.w;
        v.x = (v.x > 0.f) ? v.x : (__expf(v.x) - 1.f);
        v.y = (v.y > 0.f) ? v.y : (__expf(v.y) - 1.f);
        v.z = (v.z > 0.f) ? v.z : (__expf(v.z) - 1.f);
        v.w = (v.w > 0.f) ? v.w : (__expf(v.w) - 1.f);

        float4 hcu;
        hcu.x = __shfl_xor_sync(0xffffffffu, hc4.x, 16);
        hcu.y = __shfl_xor_sync(0xffffffffu, hc4.y, 16);
        hcu.z = __shfl_xor_sync(0xffffffffu, hc4.z, 16);
        hcu.w = __shfl_xor_sync(0xffffffffu, hc4.w, 16);
        float4 hcv = (lane < 16) ? hc4 : hcu;

        float4 linv = *(const float4*)(g_lin + R * 128 + 4 * lane);
        float a  = (lane < 16) ? 1.f : 2.f;
        float am = a - 1.f;
        float4 gt;
        {
            float p;
            p = v.x + linv.x + hcv.x; gt.x = __fdividef(a, 1.f + __expf(-a * p)) - am;
            p = v.y + linv.y + hcv.y; gt.y = __fdividef(a, 1.f + __expf(-a * p)) - am;
            p = v.z + linv.z + hcv.z; gt.z = __fdividef(a, 1.f + __expf(-a * p)) - am;
            p = v.w + linv.w + hcv.w; gt.w = __fdividef(a, 1.f + __expf(-a * p)) - am;
        }

        float4 og;
        og.x = __shfl_xor_sync(0xffffffffu, gt.x, 16);
        og.y = __shfl_xor_sync(0xffffffffu, gt.y, 16);
        og.z = __shfl_xor_sync(0xffffffffu, gt.z, 16);
        og.w = __shfl_xor_sync(0xffffffffu, gt.w, 16);

        if (lane < 16) {
            hc4.x = gt.x * hc4.x + (1.f - gt.x) * og.x;
            hc4.y = gt.y * hc4.y + (1.f - gt.y) * og.y;
            hc4.z = gt.z * hc4.z + (1.f - gt.z) * og.z;
            hc4.w = gt.w * hc4.w + (1.f - gt.w) * og.w;
        }
    }

    if (lane < 16) {
        float4 mu = *(const float4*)(bn_m + 4 * l16);
        float4 vr = *(const float4*)(bn_v + 4 * l16);
        float4 ga = *(const float4*)(bn_g + 4 * l16);
        float4 be = *(const float4*)(bn_b + 4 * l16);
        float4 o;
        o.x = (hc4.x - mu.x) * rsqrtf(vr.x + BN_EPS) * ga.x + be.x;
        o.y = (hc4.y - mu.y) * rsqrtf(vr.y + BN_EPS) * ga.y + be.y;
        o.z = (hc4.z - mu.z) * rsqrtf(vr.z + BN_EPS) * ga.z + be.z;
        o.w = (hc4.w - mu.w) * rsqrtf(vr.w + BN_EPS) * ga.w + be.w;
        *(float4*)(out + (size_t)row * CC + 4 * l16) = o;
    }
}

// =====================================================================
// launch
// =====================================================================
extern "C" void kernel_launch(void* const* d_in, const int* in_sizes, int n_in,
                              void* d_out, int out_size)
{
    const float* X      = (const float*)d_in[0];
    const float* bias   = (const float*)d_in[1];
    const float* W_z    = (const float*)d_in[2];
    const float* Z_bias = (const float*)d_in[3];
    const float* W_h    = (const float*)d_in[4];
    const float* H_bias = (const float*)d_in[5];
    const float* Wg_z   = (const float*)d_in[6];
    const float* a1_z   = (const float*)d_in[7];
    const float* a2_z   = (const float*)d_in[8];
    const float* bg_z   = (const float*)d_in[9];
    const float* Wg_h   = (const float*)d_in[10];
    const float* a1_h   = (const float*)d_in[11];
    const float* a2_h   = (const float*)d_in[12];
    const float* bg_h   = (const float*)d_in[13];
    const float* bn_g   = (const float*)d_in[14];
    const float* bn_b   = (const float*)d_in[15];
    const float* bn_m   = (const float*)d_in[16];
    const float* bn_v   = (const float*)d_in[17];
    float* out = (float*)d_out;

    prep_wfrag<<<32, 256>>>(W_z, W_h, Wg_z, Wg_h);
    gemm_tc<<<444, 256>>>(X, Z_bias, H_bias, a1_z, a2_z, a1_h, a2_h);
    fused_rnn<<<NROW / WPB, 256>>>(bias, bg_z, bg_h, bn_g, bn_b, bn_m, bn_v, out);
}